// round 4
// baseline (speedup 1.0000x reference)
#include <cuda_runtime.h>
#include <cuda_bf16.h>
#include <math.h>
#include <stdint.h>

#define TT 4096
#define KTOT (64*4096)   /* 262144 */
#define FD 512

// ---------------- scratch (static device globals) ----------------
__device__ __nv_bfloat16 g_Ah[(size_t)320 * KTOT];
__device__ __nv_bfloat16 g_Al[(size_t)320 * KTOT];
__device__ __nv_bfloat16 g_Wh[(size_t)KTOT * FD];
__device__ __nv_bfloat16 g_Wl[(size_t)KTOT * FD];
__device__ float g_feats[320 * FD];
__device__ float g_norms[320];
__device__ float g_cons;
__device__ float g_contr;

// ---------------- PTX helpers (baseline ISA only) ----------------
__device__ __forceinline__ uint32_t smem_to_u32(const void* p) {
    uint32_t a;
    asm("{ .reg .u64 t; cvta.to.shared.u64 t, %1; cvt.u32.u64 %0, t; }" : "=r"(a) : "l"(p));
    return a;
}
__device__ __forceinline__ void ldsm_x4(uint32_t* r, uint32_t addr) {
    asm volatile("ldmatrix.sync.aligned.m8n8.x4.shared.b16 {%0,%1,%2,%3}, [%4];"
        : "=r"(r[0]), "=r"(r[1]), "=r"(r[2]), "=r"(r[3]) : "r"(addr));
}
__device__ __forceinline__ void ldsm_x2_trans(uint32_t* r, uint32_t addr) {
    asm volatile("ldmatrix.sync.aligned.m8n8.x2.trans.shared.b16 {%0,%1}, [%2];"
        : "=r"(r[0]), "=r"(r[1]) : "r"(addr));
}
__device__ __forceinline__ void mma_bf16(float* c, const uint32_t* a, const uint32_t* b) {
    asm volatile("mma.sync.aligned.m16n8k16.row.col.f32.bf16.bf16.f32 "
        "{%0,%1,%2,%3}, {%4,%5,%6,%7}, {%8,%9}, {%0,%1,%2,%3};"
        : "+f"(c[0]), "+f"(c[1]), "+f"(c[2]), "+f"(c[3])
        : "r"(a[0]), "r"(a[1]), "r"(a[2]), "r"(a[3]), "r"(b[0]), "r"(b[1]));
}
__device__ __forceinline__ void cp_async16(uint32_t smem, const void* g) {
    asm volatile("cp.async.cg.shared.global [%0], [%1], 16;" :: "r"(smem), "l"(g));
}
#define CP_COMMIT() asm volatile("cp.async.commit_group;" ::: "memory")
#define CP_WAIT1()  asm volatile("cp.async.wait_group 1;" ::: "memory")
#define CP_WAIT0()  asm volatile("cp.async.wait_group 0;" ::: "memory")

// ---------------- block reductions ----------------
__device__ __forceinline__ float blockReduceSum(float v, float* red) {
    int lane = threadIdx.x & 31, w = threadIdx.x >> 5;
    int nw = blockDim.x >> 5;
    #pragma unroll
    for (int o = 16; o; o >>= 1) v += __shfl_down_sync(0xffffffffu, v, o);
    if (lane == 0) red[w] = v;
    __syncthreads();
    if (w == 0) {
        float r = (lane < nw) ? red[lane] : 0.0f;
        #pragma unroll
        for (int o = 8; o; o >>= 1) r += __shfl_down_sync(0xffffffffu, r, o);
        if (lane == 0) red[0] = r;
    }
    __syncthreads();
    float out = red[0];
    __syncthreads();
    return out;
}
__device__ __forceinline__ float blockReduceMax(float v, float* red) {
    int lane = threadIdx.x & 31, w = threadIdx.x >> 5;
    int nw = blockDim.x >> 5;
    #pragma unroll
    for (int o = 16; o; o >>= 1) v = fmaxf(v, __shfl_down_sync(0xffffffffu, v, o));
    if (lane == 0) red[w] = v;
    __syncthreads();
    if (w == 0) {
        float r = (lane < nw) ? red[lane] : -3.4e38f;
        #pragma unroll
        for (int o = 8; o; o >>= 1) r = fmaxf(r, __shfl_down_sync(0xffffffffu, r, o));
        if (lane == 0) red[0] = r;
    }
    __syncthreads();
    float out = red[0];
    __syncthreads();
    return out;
}

// ---------------- complex helpers / masks ----------------
__device__ __forceinline__ float2 cmul(float2 a, float2 b) {
    return make_float2(a.x*b.x - a.y*b.y, a.x*b.y + a.y*b.x);
}
__device__ __forceinline__ float2 cmulc(float2 a, float2 b) {   // conj(a)*b
    return make_float2(a.x*b.x + a.y*b.y, a.x*b.y - a.y*b.x);
}
template<int MID>
__device__ __forceinline__ float maskval(int k, int fs) {
    float fm = (k >= fs && k < fs + 409) ? 0.1f : 1.0f;
    if (MID == 0) return (k < 2048) ? 1.0f : 0.0f;
    if (MID == 1) return fm;
    float g = (k == 0) ? 1.0f : ((k <= 1024) ? 0.5f : ((k < 3072) ? 1.0f : 0.5f));
    return g * fm;
}

// ---------------- radix-4 Stockham FFT, N=4096 (6 stages) ----------------
// tw[k] = exp(-i*pi*k/2048), k < 3072 (indices up to 3*jm, jm < 1024)
__device__ float2* fft4_fwd(const float2* __restrict__ tw, float2* b0, float2* b1) {
    float2* src = b0; float2* dst = b1;
    #pragma unroll 1
    for (int s2 = 0; s2 < 12; s2 += 2) {
        const int m = 1 << s2;
        __syncthreads();
        #pragma unroll
        for (int i = threadIdx.x; i < 1024; i += 512) {
            int jm = (i >> s2) << s2;
            float2 e0 = src[i], e1 = src[i + 1024], e2 = src[i + 2048], e3 = src[i + 3072];
            float2 s02 = make_float2(e0.x + e2.x, e0.y + e2.y);
            float2 d02 = make_float2(e0.x - e2.x, e0.y - e2.y);
            float2 s13 = make_float2(e1.x + e3.x, e1.y + e3.y);
            float2 d13 = make_float2(e1.x - e3.x, e1.y - e3.y);
            int base = i + 3 * jm;
            dst[base]       = make_float2(s02.x + s13.x, s02.y + s13.y);
            dst[base + m]   = cmul(tw[jm],     make_float2(d02.x + d13.y, d02.y - d13.x));
            dst[base + 2*m] = cmul(tw[2 * jm], make_float2(s02.x - s13.x, s02.y - s13.y));
            dst[base + 3*m] = cmul(tw[3 * jm], make_float2(d02.x - d13.y, d02.y + d13.x));
        }
        float2* t = src; src = dst; dst = t;
    }
    __syncthreads();
    return src;  // 6 swaps -> b0
}

// masked inverse: fused mask into stage 0 (reads X, preserved), 5 more stages b1<->b2, result b2.
template<int MID>
__device__ float2* ifft4_masked(const float2* __restrict__ tw, const float2* __restrict__ X,
                                float2* b1, float2* b2, int fs) {
    __syncthreads();
    #pragma unroll
    for (int i = threadIdx.x; i < 1024; i += 512) {
        float m0 = maskval<MID>(i, fs);
        float m1 = maskval<MID>(i + 1024, fs);
        float m2 = maskval<MID>(i + 2048, fs);
        float m3 = maskval<MID>(i + 3072, fs);
        float2 e0 = X[i];        e0.x *= m0; e0.y *= m0;
        float2 e1 = X[i + 1024]; e1.x *= m1; e1.y *= m1;
        float2 e2 = X[i + 2048]; e2.x *= m2; e2.y *= m2;
        float2 e3 = X[i + 3072]; e3.x *= m3; e3.y *= m3;
        float2 s02 = make_float2(e0.x + e2.x, e0.y + e2.y);
        float2 d02 = make_float2(e0.x - e2.x, e0.y - e2.y);
        float2 s13 = make_float2(e1.x + e3.x, e1.y + e3.y);
        float2 d13 = make_float2(e1.x - e3.x, e1.y - e3.y);
        int base = 4 * i;
        b1[base]     = make_float2(s02.x + s13.x, s02.y + s13.y);
        b1[base + 1] = cmulc(tw[i],     make_float2(d02.x - d13.y, d02.y + d13.x));
        b1[base + 2] = cmulc(tw[2 * i], make_float2(s02.x - s13.x, s02.y - s13.y));
        b1[base + 3] = cmulc(tw[3 * i], make_float2(d02.x + d13.y, d02.y - d13.x));
    }
    float2* src = b1; float2* dst = b2;
    #pragma unroll 1
    for (int s2 = 2; s2 < 12; s2 += 2) {
        const int m = 1 << s2;
        __syncthreads();
        #pragma unroll
        for (int i = threadIdx.x; i < 1024; i += 512) {
            int jm = (i >> s2) << s2;
            float2 e0 = src[i], e1 = src[i + 1024], e2 = src[i + 2048], e3 = src[i + 3072];
            float2 s02 = make_float2(e0.x + e2.x, e0.y + e2.y);
            float2 d02 = make_float2(e0.x - e2.x, e0.y - e2.y);
            float2 s13 = make_float2(e1.x + e3.x, e1.y + e3.y);
            float2 d13 = make_float2(e1.x - e3.x, e1.y - e3.y);
            int base = i + 3 * jm;
            dst[base]       = make_float2(s02.x + s13.x, s02.y + s13.y);
            dst[base + m]   = cmulc(tw[jm],     make_float2(d02.x - d13.y, d02.y + d13.x));
            dst[base + 2*m] = cmulc(tw[2 * jm], make_float2(s02.x - s13.x, s02.y - s13.y));
            dst[base + 3*m] = cmulc(tw[3 * jm], make_float2(d02.x + d13.y, d02.y - d13.x));
        }
        float2* t = src; src = dst; dst = t;
    }
    __syncthreads();
    return src;  // 5 swaps from b1 -> b2
}

// ---------------- kernel 0: init ----------------
__global__ void init_kernel(const float* __restrict__ b) {
    int i = blockIdx.x * blockDim.x + threadIdx.x;
    if (i < 320 * FD) g_feats[i] = b[i & 511];
    if (i == 0) { g_cons = 0.0f; g_contr = 0.0f; }
}

// ---------------- kernel W: bf16 hi/lo split of W (layout preserved [k][n]) ----------------
__global__ void __launch_bounds__(256) wsplit_kernel(const float* __restrict__ W) {
    size_t i = ((size_t)blockIdx.x * 256 + threadIdx.x) * 8;   // 8 floats per thread
    float4 v0 = *(const float4*)(W + i);
    float4 v1 = *(const float4*)(W + i + 4);
    __align__(16) __nv_bfloat16 hi[8], lo[8];
    const float* vf = &v0.x;
    #pragma unroll
    for (int j = 0; j < 8; j++) {
        float v = (j < 4) ? vf[j] : (&v1.x)[j - 4];
        __nv_bfloat16 h = __float2bfloat16_rn(v);
        hi[j] = h;
        lo[j] = __float2bfloat16_rn(v - __bfloat162float(h));
    }
    *(float4*)(g_Wh + i) = *(float4*)hi;
    *(float4*)(g_Wl + i) = *(float4*)lo;
}

// ---------------- kernel 1: build 5 views -> bf16 hi/lo ----------------
__device__ __forceinline__ void store_hl(size_t idx, float v) {
    __nv_bfloat16 h = __float2bfloat16_rn(v);
    g_Ah[idx] = h;
    g_Al[idx] = __float2bfloat16_rn(v - __bfloat162float(h));
}

__global__ void __launch_bounds__(512, 1)
views_kernel(const float* __restrict__ x, const float* __restrict__ nz1,
             const float* __restrict__ nz2,
             const int* __restrict__ pfs, const int* __restrict__ pts) {
    extern __shared__ float2 smx[];
    float2* tw = smx;            // 3072
    float2* bA = smx + 3072;     // 4096 (holds X after fwd)
    float2* bB = bA + 4096;      // 4096
    float2* bC = bB + 4096;      // 4096
    __shared__ float red[32];

    const int row = blockIdx.x;
    const int bi = row >> 6, ci = row & 63;
    const int tid = threadIdx.x;
    const int fs = *pfs, ts = *pts;
    const size_t xbase = (size_t)row * TT;

    const size_t a0 = (size_t)(0*64 + bi) * KTOT + (size_t)ci * TT;
    const size_t a1 = (size_t)(1*64 + bi) * KTOT + (size_t)ci * TT;
    const size_t a2 = (size_t)(2*64 + bi) * KTOT + (size_t)ci * TT;
    const size_t a3 = (size_t)(3*64 + bi) * KTOT + (size_t)ci * TT;
    const size_t a4 = (size_t)(4*64 + bi) * KTOT + (size_t)ci * TT;

    for (int k = tid; k < 3072; k += 512) {
        float s, c;
        sincospif(-(float)k * (1.0f / 2048.0f), &s, &c);
        tw[k] = make_float2(c, s);
    }

    float ls = 0.0f, lq = 0.0f;
    for (int t = tid; t < TT; t += 512) {
        float v = x[xbase + t];
        bA[t] = make_float2(v, 0.0f);
        store_hl(a0 + t, v);
        ls += v; lq += v * v;
    }
    float s1 = blockReduceSum(ls, red);
    float q1 = blockReduceSum(lq, red);
    float std1 = sqrtf(fmaxf(0.0f, (q1 - s1 * s1 * (1.0f / 4096.0f)) * (1.0f / 4095.0f)));

    for (int t = tid; t < TT; t += 512)
        store_hl(a3 + t, x[xbase + t] + nz1[xbase + t] * (0.02f * std1));

    fft4_fwd(tw, bA, bB);   // X in bA

    float2* r = ifft4_masked<0>(tw, bA, bB, bC, fs);
    for (int t = tid; t < TT; t += 512)
        store_hl(a1 + t, r[t].x * (1.0f / 4096.0f));

    r = ifft4_masked<1>(tw, bA, bB, bC, fs);
    for (int t = tid; t < TT; t += 512) {
        float tm = (t >= ts && t < ts + 204) ? 0.1f : 1.0f;
        store_hl(a2 + t, tm * r[t].x * (1.0f / 4096.0f));
    }

    r = ifft4_masked<2>(tw, bA, bB, bC, fs);
    ls = 0.0f; lq = 0.0f;
    for (int t = tid; t < TT; t += 512) {
        float tm = (t >= ts && t < ts + 204) ? 0.1f : 1.0f;
        float v = tm * r[t].x * (1.0f / 4096.0f);
        ls += v; lq += v * v;
    }
    float s2 = blockReduceSum(ls, red);
    float q2 = blockReduceSum(lq, red);
    float std2 = sqrtf(fmaxf(0.0f, (q2 - s2 * s2 * (1.0f / 4096.0f)) * (1.0f / 4095.0f)));
    for (int t = tid; t < TT; t += 512) {
        float tm = (t >= ts && t < ts + 204) ? 0.1f : 1.0f;
        float v = tm * r[t].x * (1.0f / 4096.0f);
        store_hl(a4 + t, v + nz2[xbase + t] * (0.02f * std2));
    }
}

// ---------------- kernel 2: async-pipelined mma.sync bf16-split GEMM ----------------
// feats[320,512] += A*W, 3-term hi/lo split; CTA tile 64x128, k-chunk 32, double-buffered.
// stage layout (24576 B): AH[0,4K) AL[4K,8K) WH[8K,16K) WL[16K,24K)
#define STG 24576

__global__ void __launch_bounds__(128, 3) gemm_kernel() {
    __shared__ __align__(1024) char smbuf[2 * STG];
    const uint32_t sb = smem_to_u32(smbuf);

    const int tid = threadIdx.x;
    const int warp = tid >> 5, lane = tid & 31;
    const int m0 = blockIdx.y * 64;
    const int n0 = blockIdx.x * 128;
    const int z = blockIdx.z;
    const int start_chunk = 372 * z + (z < 8 ? z : 8);
    const int nchunks = 372 + (z < 8 ? 1 : 0);

    const int wm = warp >> 1;
    const int wn = warp & 1;

    float acc[2][8][4];
    #pragma unroll
    for (int a = 0; a < 2; a++)
        #pragma unroll
        for (int b = 0; b < 8; b++)
            #pragma unroll
            for (int c = 0; c < 4; c++) acc[a][b][c] = 0.0f;

    // ---- cp.async source pointers + dst offsets ----
    // A: 256 16B-chunks/plane: f = tid + 128*i -> m=f>>2, kc=f&3
    const __nv_bfloat16* srcA[4];
    uint32_t dstA[4];
    #pragma unroll
    for (int i = 0; i < 2; i++) {
        int f = tid + 128 * i;
        int m = f >> 2, kc = f & 3;
        uint32_t rel = (uint32_t)(m * 64 + (((kc + (m >> 1)) & 3) << 4));
        size_t src = (size_t)(m0 + m) * KTOT + (size_t)start_chunk * 32 + kc * 8;
        dstA[i] = rel;            srcA[i] = g_Ah + src;
        dstA[i + 2] = rel + 4096; srcA[i + 2] = g_Al + src;
    }
    // W: 512 16B-chunks/plane: f = tid + 128*i -> k=f>>4, nc=f&15
    const __nv_bfloat16* srcW[8];
    uint32_t dstW[8];
    #pragma unroll
    for (int i = 0; i < 4; i++) {
        int f = tid + 128 * i;
        int k = f >> 4, nc = f & 15;
        uint32_t rel = (uint32_t)(8192 + k * 256 + (((nc ^ (k & 7)) & 15) << 4));
        size_t src = ((size_t)start_chunk * 32 + k) * 512 + n0 + nc * 8;
        dstW[i] = rel;            srcW[i] = g_Wh + src;
        dstW[i + 4] = rel + 8192; srcW[i + 4] = g_Wl + src;
    }

    // ---- ldmatrix addresses (relative to stage base) ----
    uint32_t a_ld[2][2];
    {
        int tile = lane >> 3, r = lane & 7;
        #pragma unroll
        for (int mt = 0; mt < 2; mt++)
            #pragma unroll
            for (int kt = 0; kt < 2; kt++) {
                int mm = wm * 32 + mt * 16 + (tile & 1) * 8 + r;
                int kb = kt * 2 + (tile >> 1);
                a_ld[mt][kt] = (uint32_t)(mm * 64 + (((kb + (mm >> 1)) & 3) << 4));
            }
    }
    uint32_t b_ld[8][2];
    {
        int lr = lane & 15;
        #pragma unroll
        for (int nt = 0; nt < 8; nt++) {
            int nb = wn * 8 + nt;
            #pragma unroll
            for (int kt = 0; kt < 2; kt++) {
                int k = kt * 16 + lr;
                b_ld[nt][kt] = (uint32_t)(8192 + k * 256 + (((nb ^ (k & 7)) & 15) << 4));
            }
        }
    }

    // ---- issue helper ----
    auto issue = [&](uint32_t sbase) {
        #pragma unroll
        for (int i = 0; i < 4; i++) {
            cp_async16(sb + sbase + dstA[i], srcA[i]);
            srcA[i] += 32;
        }
        #pragma unroll
        for (int i = 0; i < 8; i++) {
            cp_async16(sb + sbase + dstW[i], srcW[i]);
            srcW[i] += 32 * 512;
        }
    };

    // ---- pipelined main loop ----
    issue(0);
    CP_COMMIT();
    for (int it = 0; it < nchunks; ++it) {
        const uint32_t cbase = (it & 1) ? STG : 0;
        if (it + 1 < nchunks) {
            issue((it & 1) ? 0 : STG);
            CP_COMMIT();
            CP_WAIT1();
        } else {
            CP_WAIT0();
        }
        __syncthreads();

        #pragma unroll
        for (int kt = 0; kt < 2; kt++) {
            uint32_t ah[2][4], al[2][4];
            #pragma unroll
            for (int mt = 0; mt < 2; mt++) {
                ldsm_x4(ah[mt], sb + cbase + a_ld[mt][kt]);
                ldsm_x4(al[mt], sb + cbase + a_ld[mt][kt] + 4096);
            }
            uint32_t bh[8][2], bl[8][2];
            #pragma unroll
            for (int nt = 0; nt < 8; nt++) {
                ldsm_x2_trans(bh[nt], sb + cbase + b_ld[nt][kt]);
                ldsm_x2_trans(bl[nt], sb + cbase + b_ld[nt][kt] + 8192);
            }
            #pragma unroll
            for (int mt = 0; mt < 2; mt++)
                #pragma unroll
                for (int nt = 0; nt < 8; nt++) {
                    mma_bf16(acc[mt][nt], ah[mt], bh[nt]);
                    mma_bf16(acc[mt][nt], ah[mt], bl[nt]);
                    mma_bf16(acc[mt][nt], al[mt], bh[nt]);
                }
        }
        __syncthreads();
    }

    // ---- epilogue: atomic accumulate ----
    {
        const int g = lane >> 2, t4 = lane & 3;
        #pragma unroll
        for (int mt = 0; mt < 2; mt++) {
            int r0 = m0 + wm * 32 + mt * 16 + g;
            int r1 = r0 + 8;
            #pragma unroll
            for (int nt = 0; nt < 8; nt++) {
                int col = n0 + wn * 64 + nt * 8 + t4 * 2;
                atomicAdd(&g_feats[r0 * 512 + col],     acc[mt][nt][0]);
                atomicAdd(&g_feats[r0 * 512 + col + 1], acc[mt][nt][1]);
                atomicAdd(&g_feats[r1 * 512 + col],     acc[mt][nt][2]);
                atomicAdd(&g_feats[r1 * 512 + col + 1], acc[mt][nt][3]);
            }
        }
    }
}

// ---------------- kernel 3: row norms + consistency ----------------
__global__ void post_kernel() {
    __shared__ float red[32];
    const int i = blockIdx.x;
    const int tid = threadIdx.x;
    const int base = i * 512;
    const int b0 = (i & 63) * 512;
    float sq = 0.0f, dsq = 0.0f;
    for (int f = tid; f < 512; f += 256) {
        float v = g_feats[base + f];
        sq += v * v;
        if (i >= 64) {
            float d = v - g_feats[b0 + f];
            dsq += d * d;
        }
    }
    float tsq = blockReduceSum(sq, red);
    float tdq = blockReduceSum(dsq, red);
    if (tid == 0) {
        g_norms[i] = sqrtf(tsq);
        if (i >= 64) atomicAdd(&g_cons, tdq);
    }
}

// ---------------- kernel 4: contrastive ----------------
__global__ void contr_kernel() {
    __shared__ float fi[512];
    __shared__ float simb[320];
    __shared__ float red[32];
    const int i = blockIdx.x;
    const int tid = threadIdx.x;
    for (int f = tid; f < 512; f += 256) fi[f] = g_feats[i * 512 + f];
    __syncthreads();
    const float inv_i = 1.0f / g_norms[i];
    const int w = tid >> 5, lane = tid & 31;
    for (int j = w; j < 320; j += 8) {
        float s = 0.0f;
        const float* fj = g_feats + j * 512;
        #pragma unroll 4
        for (int e = lane; e < 512; e += 32) s += fi[e] * fj[e];
        #pragma unroll
        for (int o = 16; o; o >>= 1) s += __shfl_down_sync(0xffffffffu, s, o);
        if (lane == 0) simb[j] = s * inv_i / g_norms[j] * 10.0f;
    }
    __syncthreads();
    float mx = -3.4e38f;
    for (int j = tid; j < 320; j += 256) mx = fmaxf(mx, simb[j]);
    mx = blockReduceMax(mx, red);
    float se = 0.0f;
    for (int j = tid; j < 320; j += 256) se += expf(simb[j] - mx);
    se = blockReduceSum(se, red);
    if (tid == 0) {
        float lse = mx + logf(se);
        float c = 0.0f;
        if (i > 0)   c += lse - simb[i - 1];
        if (i < 319) c += lse - simb[i + 1];
        atomicAdd(&g_contr, c);
    }
}

// ---------------- kernel 5: finalize ----------------
__global__ void fin_kernel(float* __restrict__ out) {
    out[0] = g_cons * (1.0f / 131072.0f) + 0.5f * (g_contr * (1.0f / 638.0f));
}

// ---------------- launch ----------------
extern "C" void kernel_launch(void* const* d_in, const int* in_sizes, int n_in,
                              void* d_out, int out_size) {
    const float* x  = (const float*)d_in[0];
    const float* W  = (const float*)d_in[1];
    const float* b  = (const float*)d_in[2];
    const float* n1 = (const float*)d_in[3];
    const float* n2 = (const float*)d_in[4];
    const int* fs   = (const int*)d_in[5];
    const int* ts   = (const int*)d_in[6];
    (void)in_sizes; (void)n_in; (void)out_size;

    cudaFuncSetAttribute(views_kernel, cudaFuncAttributeMaxDynamicSharedMemorySize, 122880);

    init_kernel<<<640, 256>>>(b);
    wsplit_kernel<<<(KTOT * FD) / (256 * 8), 256>>>(W);
    views_kernel<<<4096, 512, 122880>>>(x, n1, n2, fs, ts);
    gemm_kernel<<<dim3(4, 5, 22), 128>>>();
    post_kernel<<<320, 256>>>();
    contr_kernel<<<320, 256>>>();
    fin_kernel<<<1, 1>>>((float*)d_out);
}